// round 14
// baseline (speedup 1.0000x reference)
#include <cuda_runtime.h>
#include <cuda_bf16.h>
#include <cstdint>

#define BB 256
#define NN 256
#define MM 256
#define DD 1024
#define RBAND 128
#define BIGF 1e30f

// dist row-major [b][i][j]
__device__ float g_dist[(size_t)BB * 256 * 256];

static __device__ __forceinline__ uint32_t smem_u32(const void* p) {
    uint32_t a;
    asm("{ .reg .u64 t; cvta.to.shared.u64 t, %1; cvt.u32.u64 %0, t; }" : "=r"(a) : "l"(p));
    return a;
}
static __device__ __forceinline__ void cp16(uint32_t dst, const void* src) {
    asm volatile("cp.async.cg.shared.global [%0], [%1], 16;\n" ::"r"(dst), "l"(src) : "memory");
}
static __device__ __forceinline__ void ldsm_x4(uint32_t& r0, uint32_t& r1, uint32_t& r2,
                                               uint32_t& r3, uint32_t addr) {
    asm volatile("ldmatrix.sync.aligned.m8n8.x4.shared.b16 {%0,%1,%2,%3}, [%4];"
                 : "=r"(r0), "=r"(r1), "=r"(r2), "=r"(r3) : "r"(addr));
}
static __device__ __forceinline__ uint2 cvt_f4_bf16(float4 a) {
    __nv_bfloat162 p0 = __floats2bfloat162_rn(a.x, a.y);
    __nv_bfloat162 p1 = __floats2bfloat162_rn(a.z, a.w);
    uint2 w;
    w.x = *reinterpret_cast<unsigned int*>(&p0);
    w.y = *reinterpret_cast<unsigned int*>(&p1);
    return w;
}

// ---------------------------------------------------------------------------
// Fused kernel (R11 base): normalization + batched GEMM with cp.async fp32
// staging, PLUS warp-level band skip: warp regions entirely outside the DTW
// band (|i-j| > 128) skip LDSM/MMA/epilogue (4 of 32 warps per batch).
// ---------------------------------------------------------------------------
#define KT 32
#define LDP 40
#define STG (128 * 32)
#define BF  (128 * LDP)
#define SM_STAGEA 0
#define SM_STAGEB (2 * STG * 4)
#define SM_AS     (4 * STG * 4)
#define SM_BS     (SM_AS + 2 * BF * 2)
#define SM_INVA   (SM_BS + 2 * BF * 2)
#define SM_INVB   (SM_INVA + 128 * 4)
#define GEMM_SMEM (SM_INVB + 128 * 4)

__global__ __launch_bounds__(256, 2) void gemm_kernel(const float* __restrict__ s1,
                                                      const float* __restrict__ s2) {
    extern __shared__ __align__(16) char sm[];
    float* stageA = (float*)(sm + SM_STAGEA);
    float* stageB = (float*)(sm + SM_STAGEB);
    __nv_bfloat16* As = (__nv_bfloat16*)(sm + SM_AS);
    __nv_bfloat16* Bs = (__nv_bfloat16*)(sm + SM_BS);
    float* invA_s = (float*)(sm + SM_INVA);
    float* invB_s = (float*)(sm + SM_INVB);

    int b  = blockIdx.z;
    int i0 = blockIdx.x * 128;
    int j0 = blockIdx.y * 128;
    int t    = threadIdx.x;
    int lane = t & 31;
    int w    = t >> 5;
    int wm = w & 1;
    int wn = w >> 1;
    int gid = lane >> 2;
    int tig = lane & 3;

    // Warp region: i in [i0+wm*64, +64), j in [j0+wn*32, +32).
    // Entirely out-of-band (|i-j| > RBAND) -> skip MMA + epilogue.
    bool skip_mma = ((blockIdx.x == 1 && blockIdx.y == 0 && wm == 1 && wn < 2) ||
                     (blockIdx.x == 0 && blockIdx.y == 1 && wm == 0 && wn >= 2));

    const float* Ag = s1 + (size_t)b * NN * DD + (size_t)i0 * DD;
    const float* Bg = s2 + (size_t)b * MM * DD + (size_t)j0 * DD;

    int lr = t >> 3;
    int lc = (t & 7) * 4;

    float acc[4][4][4];
#pragma unroll
    for (int mt = 0; mt < 4; mt++)
#pragma unroll
        for (int nt = 0; nt < 4; nt++)
#pragma unroll
            for (int c = 0; c < 4; c++) acc[mt][nt][c] = 0.f;

    float ssA[4] = {0.f, 0.f, 0.f, 0.f};
    float ssB[4] = {0.f, 0.f, 0.f, 0.f};

#pragma unroll
    for (int s = 0; s < 2; s++) {
#pragma unroll
        for (int r4 = 0; r4 < 4; r4++) {
            int row = lr + r4 * 32;
            cp16(smem_u32(&stageA[s * STG + row * 32 + lc]),
                 Ag + (size_t)row * DD + s * KT + lc);
            cp16(smem_u32(&stageB[s * STG + row * 32 + lc]),
                 Bg + (size_t)row * DD + s * KT + lc);
        }
        asm volatile("cp.async.commit_group;\n" ::: "memory");
    }

    int a_row_in = (lane & 15);
    int a_koff   = (lane >> 4) * 8;
    int b_row_in = ((lane >> 4) << 3) + (lane & 7);
    int b_koff   = ((lane >> 3) & 1) * 8;

    for (int kt = 0; kt < DD / KT; kt++) {
        int st = kt & 1;
        if (kt >= 30) {
            asm volatile("cp.async.wait_group 0;\n" ::: "memory");
        } else {
            asm volatile("cp.async.wait_group 1;\n" ::: "memory");
        }

#pragma unroll
        for (int r4 = 0; r4 < 4; r4++) {
            int row = lr + r4 * 32;
            float4 a4 = *(const float4*)&stageA[st * STG + row * 32 + lc];
            float4 b4 = *(const float4*)&stageB[st * STG + row * 32 + lc];
            ssA[r4] += a4.x * a4.x + a4.y * a4.y + a4.z * a4.z + a4.w * a4.w;
            ssB[r4] += b4.x * b4.x + b4.y * b4.y + b4.z * b4.z + b4.w * b4.w;
            *(uint2*)&As[st * BF + row * LDP + lc] = cvt_f4_bf16(a4);
            *(uint2*)&Bs[st * BF + row * LDP + lc] = cvt_f4_bf16(b4);
        }

        if (kt + 2 < DD / KT) {
#pragma unroll
            for (int r4 = 0; r4 < 4; r4++) {
                int row = lr + r4 * 32;
                cp16(smem_u32(&stageA[st * STG + row * 32 + lc]),
                     Ag + (size_t)row * DD + (kt + 2) * KT + lc);
                cp16(smem_u32(&stageB[st * STG + row * 32 + lc]),
                     Bg + (size_t)row * DD + (kt + 2) * KT + lc);
            }
            asm volatile("cp.async.commit_group;\n" ::: "memory");
        }

        __syncthreads();

        if (!skip_mma) {
#pragma unroll
            for (int kk = 0; kk < KT; kk += 16) {
                uint32_t af[4][4];
                uint32_t bf2[2][4];
#pragma unroll
                for (int mt = 0; mt < 4; mt++) {
                    int arow = wm * 64 + mt * 16 + a_row_in;
                    uint32_t addr = smem_u32(&As[st * BF + arow * LDP + kk + a_koff]);
                    ldsm_x4(af[mt][0], af[mt][1], af[mt][2], af[mt][3], addr);
                }
#pragma unroll
                for (int ntp = 0; ntp < 2; ntp++) {
                    int brow = wn * 32 + ntp * 16 + b_row_in;
                    uint32_t addr = smem_u32(&Bs[st * BF + brow * LDP + kk + b_koff]);
                    ldsm_x4(bf2[ntp][0], bf2[ntp][1], bf2[ntp][2], bf2[ntp][3], addr);
                }
#pragma unroll
                for (int mt = 0; mt < 4; mt++)
#pragma unroll
                    for (int nt = 0; nt < 4; nt++) {
                        uint32_t b0 = bf2[nt >> 1][(nt & 1) * 2];
                        uint32_t b1 = bf2[nt >> 1][(nt & 1) * 2 + 1];
                        asm volatile(
                            "mma.sync.aligned.m16n8k16.row.col.f32.bf16.bf16.f32 "
                            "{%0,%1,%2,%3}, {%4,%5,%6,%7}, {%8,%9}, {%0,%1,%2,%3};\n"
                            : "+f"(acc[mt][nt][0]), "+f"(acc[mt][nt][1]),
                              "+f"(acc[mt][nt][2]), "+f"(acc[mt][nt][3])
                            : "r"(af[mt][0]), "r"(af[mt][1]), "r"(af[mt][2]), "r"(af[mt][3]),
                              "r"(b0), "r"(b1));
                    }
            }
        }
    }

#pragma unroll
    for (int r4 = 0; r4 < 4; r4++) {
#pragma unroll
        for (int o = 1; o < 8; o <<= 1) {
            ssA[r4] += __shfl_xor_sync(0xffffffffu, ssA[r4], o);
            ssB[r4] += __shfl_xor_sync(0xffffffffu, ssB[r4], o);
        }
        if ((lane & 7) == 0) {
            int row = lr + r4 * 32;
            invA_s[row] = 1.0f / fmaxf(sqrtf(ssA[r4]), 1e-12f);
            invB_s[row] = 1.0f / fmaxf(sqrtf(ssB[r4]), 1e-12f);
        }
    }
    __syncthreads();

    if (!skip_mma) {
        float* dT = g_dist + (size_t)b * 65536;
#pragma unroll
        for (int mt = 0; mt < 4; mt++) {
#pragma unroll
            for (int nt = 0; nt < 4; nt++) {
                int li = wm * 64 + mt * 16 + gid;
                int lj = wn * 32 + nt * 8 + tig * 2;
                float ia0 = invA_s[li];
                float ia1 = invA_s[li + 8];
                float ib0 = invB_s[lj];
                float ib1 = invB_s[lj + 1];
                float2 v0, v1;
                v0.x = 1.0f - fminf(fmaxf(acc[mt][nt][0] * ia0 * ib0, -1.f), 1.f);
                v0.y = 1.0f - fminf(fmaxf(acc[mt][nt][1] * ia0 * ib1, -1.f), 1.f);
                v1.x = 1.0f - fminf(fmaxf(acc[mt][nt][2] * ia1 * ib0, -1.f), 1.f);
                v1.y = 1.0f - fminf(fmaxf(acc[mt][nt][3] * ia1 * ib1, -1.f), 1.f);
                int i = i0 + li;
                int j = j0 + lj;
                *(float2*)&dT[(size_t)i * 256 + j]       = v0;
                *(float2*)&dT[(size_t)(i + 8) * 256 + j] = v1;
            }
        }
    }
}

// ---------------------------------------------------------------------------
// Kernel 2: banded DTW — systolic staircase (R12 base) with the `act`
// predication REMOVED from the loop-carried chain: invalid prefetch slots are
// zero-initialized so inactive rows self-propagate BIG (BIG + 0 = BIG); rows
// r > 255 compute garbage that nobody reads (result captured at r == 255,
// neighbors only consume values committed for r <= 255).
// ---------------------------------------------------------------------------
__global__ __launch_bounds__(128) void dtw_kernel(float* __restrict__ out) {
    int w     = threadIdx.x >> 5;
    int lane  = threadIdx.x & 31;
    int batch = blockIdx.x * 4 + w;
    const float* E = g_dist + (size_t)batch * 65536;
    int jb = lane * 8;

    float d1[8];
#pragma unroll
    for (int u = 0; u < 8; u++) d1[u] = BIGF;
    float last7 = BIGF, prev7 = BIGF;
    float result = 0.f;

    float4 pf[8][2];
#pragma unroll
    for (int p = 0; p < 8; p++) {
        int r = p - lane;
        if (r >= 0) {
            const float* src = E + (size_t)r * 256 + jb;
            pf[p][0] = *(const float4*)src;
            pf[p][1] = *(const float4*)(src + 4);
        } else {
            pf[p][0] = make_float4(0.f, 0.f, 0.f, 0.f);
            pf[p][1] = make_float4(0.f, 0.f, 0.f, 0.f);
        }
    }

#pragma unroll 1
    for (int tb = 0; tb < 288; tb += 8) {
#pragma unroll
        for (int p = 0; p < 8; p++) {
            int t = tb + p;
            int r = t - lane;

            float e[8];
            e[0] = pf[p][0].x; e[1] = pf[p][0].y; e[2] = pf[p][0].z; e[3] = pf[p][0].w;
            e[4] = pf[p][1].x; e[5] = pf[p][1].y; e[6] = pf[p][1].z; e[7] = pf[p][1].w;

            {
                int rl = r + 8;
                if ((unsigned)rl < 256u) {
                    const float* src = E + (size_t)rl * 256 + jb;
                    pf[p][0] = *(const float4*)src;
                    pf[p][1] = *(const float4*)(src + 4);
                }
            }

            float lf0 = __shfl_up_sync(0xffffffffu, last7, 1);  // (r,   jb-1)
            float ul0 = __shfl_up_sync(0xffffffffu, prev7, 1);  // (r-1, jb-1)

            float m[8];
            m[0] = fminf(d1[0], ul0);
#pragma unroll
            for (int u = 1; u < 8; u++) m[u] = fminf(d1[u], d1[u - 1]);

            float nv[8];
            if (lane == 0) {
                nv[0] = (r == 0) ? e[0] : ((r <= RBAND) ? d1[0] + e[0] : BIGF);
            } else {
                bool ib = (jb >= r - RBAND) && (jb <= r + RBAND);
                nv[0] = ib ? fminf(m[0], lf0) + e[0] : BIGF;
            }
#pragma unroll
            for (int u = 1; u < 8; u++) {
                int j = jb + u;
                bool ib = (j >= r - RBAND) && (j <= r + RBAND);
                nv[u] = ib ? fminf(m[u], nv[u - 1]) + e[u] : BIGF;
            }

#pragma unroll
            for (int u = 0; u < 8; u++) d1[u] = nv[u];
            prev7 = last7;
            last7 = nv[7];
            if (r == 255) result = nv[7];
        }
    }

    if (lane == 31) out[batch] = result;
}

// ---------------------------------------------------------------------------
extern "C" void kernel_launch(void* const* d_in, const int* in_sizes, int n_in,
                              void* d_out, int out_size) {
    const float* s1 = (const float*)d_in[0];
    const float* s2 = (const float*)d_in[1];
    float* out = (float*)d_out;

    cudaFuncSetAttribute(gemm_kernel, cudaFuncAttributeMaxDynamicSharedMemorySize, GEMM_SMEM);
    dim3 g(2, 2, BB);
    gemm_kernel<<<g, 256, GEMM_SMEM>>>(s1, s2);

    dtw_kernel<<<64, 128>>>(out);
}

// round 15
// speedup vs baseline: 1.0639x; 1.0639x over previous
#include <cuda_runtime.h>
#include <cuda_bf16.h>
#include <cstdint>

#define BB 256
#define NN 256
#define MM 256
#define DD 1024
#define RBAND 128
#define BIGF 1e30f

// dist row-major [b][i][j]
__device__ float g_dist[(size_t)BB * 256 * 256];

static __device__ __forceinline__ uint32_t smem_u32(const void* p) {
    uint32_t a;
    asm("{ .reg .u64 t; cvta.to.shared.u64 t, %1; cvt.u32.u64 %0, t; }" : "=r"(a) : "l"(p));
    return a;
}
static __device__ __forceinline__ void cp16(uint32_t dst, const void* src) {
    asm volatile("cp.async.cg.shared.global [%0], [%1], 16;\n" ::"r"(dst), "l"(src) : "memory");
}
static __device__ __forceinline__ void ldsm_x4(uint32_t& r0, uint32_t& r1, uint32_t& r2,
                                               uint32_t& r3, uint32_t addr) {
    asm volatile("ldmatrix.sync.aligned.m8n8.x4.shared.b16 {%0,%1,%2,%3}, [%4];"
                 : "=r"(r0), "=r"(r1), "=r"(r2), "=r"(r3) : "r"(addr));
}
static __device__ __forceinline__ uint2 cvt_f4_bf16(float4 a) {
    __nv_bfloat162 p0 = __floats2bfloat162_rn(a.x, a.y);
    __nv_bfloat162 p1 = __floats2bfloat162_rn(a.z, a.w);
    uint2 w;
    w.x = *reinterpret_cast<unsigned int*>(&p0);
    w.y = *reinterpret_cast<unsigned int*>(&p1);
    return w;
}

// ---------------------------------------------------------------------------
// Fused kernel (R11 exact — best validated GEMM, ~150us): normalization +
// batched GEMM with cp.async fp32 staging ring; convert+ss at the wait site;
// epilogue applies 1/(|x||y|), clamps, stores dist row-major as float2.
// ---------------------------------------------------------------------------
#define KT 32
#define LDP 40
#define STG (128 * 32)
#define BF  (128 * LDP)
#define SM_STAGEA 0
#define SM_STAGEB (2 * STG * 4)
#define SM_AS     (4 * STG * 4)
#define SM_BS     (SM_AS + 2 * BF * 2)
#define SM_INVA   (SM_BS + 2 * BF * 2)
#define SM_INVB   (SM_INVA + 128 * 4)
#define GEMM_SMEM (SM_INVB + 128 * 4)

__global__ __launch_bounds__(256, 2) void gemm_kernel(const float* __restrict__ s1,
                                                      const float* __restrict__ s2) {
    extern __shared__ __align__(16) char sm[];
    float* stageA = (float*)(sm + SM_STAGEA);
    float* stageB = (float*)(sm + SM_STAGEB);
    __nv_bfloat16* As = (__nv_bfloat16*)(sm + SM_AS);
    __nv_bfloat16* Bs = (__nv_bfloat16*)(sm + SM_BS);
    float* invA_s = (float*)(sm + SM_INVA);
    float* invB_s = (float*)(sm + SM_INVB);

    int b  = blockIdx.z;
    int i0 = blockIdx.x * 128;
    int j0 = blockIdx.y * 128;
    int t    = threadIdx.x;
    int lane = t & 31;
    int w    = t >> 5;
    int wm = w & 1;
    int wn = w >> 1;
    int gid = lane >> 2;
    int tig = lane & 3;

    const float* Ag = s1 + (size_t)b * NN * DD + (size_t)i0 * DD;
    const float* Bg = s2 + (size_t)b * MM * DD + (size_t)j0 * DD;

    int lr = t >> 3;
    int lc = (t & 7) * 4;

    float acc[4][4][4];
#pragma unroll
    for (int mt = 0; mt < 4; mt++)
#pragma unroll
        for (int nt = 0; nt < 4; nt++)
#pragma unroll
            for (int c = 0; c < 4; c++) acc[mt][nt][c] = 0.f;

    float ssA[4] = {0.f, 0.f, 0.f, 0.f};
    float ssB[4] = {0.f, 0.f, 0.f, 0.f};

#pragma unroll
    for (int s = 0; s < 2; s++) {
#pragma unroll
        for (int r4 = 0; r4 < 4; r4++) {
            int row = lr + r4 * 32;
            cp16(smem_u32(&stageA[s * STG + row * 32 + lc]),
                 Ag + (size_t)row * DD + s * KT + lc);
            cp16(smem_u32(&stageB[s * STG + row * 32 + lc]),
                 Bg + (size_t)row * DD + s * KT + lc);
        }
        asm volatile("cp.async.commit_group;\n" ::: "memory");
    }

    int a_row_in = (lane & 15);
    int a_koff   = (lane >> 4) * 8;
    int b_row_in = ((lane >> 4) << 3) + (lane & 7);
    int b_koff   = ((lane >> 3) & 1) * 8;

    for (int kt = 0; kt < DD / KT; kt++) {
        int st = kt & 1;
        if (kt >= 30) {
            asm volatile("cp.async.wait_group 0;\n" ::: "memory");
        } else {
            asm volatile("cp.async.wait_group 1;\n" ::: "memory");
        }

#pragma unroll
        for (int r4 = 0; r4 < 4; r4++) {
            int row = lr + r4 * 32;
            float4 a4 = *(const float4*)&stageA[st * STG + row * 32 + lc];
            float4 b4 = *(const float4*)&stageB[st * STG + row * 32 + lc];
            ssA[r4] += a4.x * a4.x + a4.y * a4.y + a4.z * a4.z + a4.w * a4.w;
            ssB[r4] += b4.x * b4.x + b4.y * b4.y + b4.z * b4.z + b4.w * b4.w;
            *(uint2*)&As[st * BF + row * LDP + lc] = cvt_f4_bf16(a4);
            *(uint2*)&Bs[st * BF + row * LDP + lc] = cvt_f4_bf16(b4);
        }

        if (kt + 2 < DD / KT) {
#pragma unroll
            for (int r4 = 0; r4 < 4; r4++) {
                int row = lr + r4 * 32;
                cp16(smem_u32(&stageA[st * STG + row * 32 + lc]),
                     Ag + (size_t)row * DD + (kt + 2) * KT + lc);
                cp16(smem_u32(&stageB[st * STG + row * 32 + lc]),
                     Bg + (size_t)row * DD + (kt + 2) * KT + lc);
            }
            asm volatile("cp.async.commit_group;\n" ::: "memory");
        }

        __syncthreads();

#pragma unroll
        for (int kk = 0; kk < KT; kk += 16) {
            uint32_t af[4][4];
            uint32_t bf2[2][4];
#pragma unroll
            for (int mt = 0; mt < 4; mt++) {
                int arow = wm * 64 + mt * 16 + a_row_in;
                uint32_t addr = smem_u32(&As[st * BF + arow * LDP + kk + a_koff]);
                ldsm_x4(af[mt][0], af[mt][1], af[mt][2], af[mt][3], addr);
            }
#pragma unroll
            for (int ntp = 0; ntp < 2; ntp++) {
                int brow = wn * 32 + ntp * 16 + b_row_in;
                uint32_t addr = smem_u32(&Bs[st * BF + brow * LDP + kk + b_koff]);
                ldsm_x4(bf2[ntp][0], bf2[ntp][1], bf2[ntp][2], bf2[ntp][3], addr);
            }
#pragma unroll
            for (int mt = 0; mt < 4; mt++)
#pragma unroll
                for (int nt = 0; nt < 4; nt++) {
                    uint32_t b0 = bf2[nt >> 1][(nt & 1) * 2];
                    uint32_t b1 = bf2[nt >> 1][(nt & 1) * 2 + 1];
                    asm volatile(
                        "mma.sync.aligned.m16n8k16.row.col.f32.bf16.bf16.f32 "
                        "{%0,%1,%2,%3}, {%4,%5,%6,%7}, {%8,%9}, {%0,%1,%2,%3};\n"
                        : "+f"(acc[mt][nt][0]), "+f"(acc[mt][nt][1]),
                          "+f"(acc[mt][nt][2]), "+f"(acc[mt][nt][3])
                        : "r"(af[mt][0]), "r"(af[mt][1]), "r"(af[mt][2]), "r"(af[mt][3]),
                          "r"(b0), "r"(b1));
                }
        }
    }

#pragma unroll
    for (int r4 = 0; r4 < 4; r4++) {
#pragma unroll
        for (int o = 1; o < 8; o <<= 1) {
            ssA[r4] += __shfl_xor_sync(0xffffffffu, ssA[r4], o);
            ssB[r4] += __shfl_xor_sync(0xffffffffu, ssB[r4], o);
        }
        if ((lane & 7) == 0) {
            int row = lr + r4 * 32;
            invA_s[row] = 1.0f / fmaxf(sqrtf(ssA[r4]), 1e-12f);
            invB_s[row] = 1.0f / fmaxf(sqrtf(ssB[r4]), 1e-12f);
        }
    }
    __syncthreads();

    float* dT = g_dist + (size_t)b * 65536;
#pragma unroll
    for (int mt = 0; mt < 4; mt++) {
#pragma unroll
        for (int nt = 0; nt < 4; nt++) {
            int li = wm * 64 + mt * 16 + gid;
            int lj = wn * 32 + nt * 8 + tig * 2;
            float ia0 = invA_s[li];
            float ia1 = invA_s[li + 8];
            float ib0 = invB_s[lj];
            float ib1 = invB_s[lj + 1];
            float2 v0, v1;
            v0.x = 1.0f - fminf(fmaxf(acc[mt][nt][0] * ia0 * ib0, -1.f), 1.f);
            v0.y = 1.0f - fminf(fmaxf(acc[mt][nt][1] * ia0 * ib1, -1.f), 1.f);
            v1.x = 1.0f - fminf(fmaxf(acc[mt][nt][2] * ia1 * ib0, -1.f), 1.f);
            v1.y = 1.0f - fminf(fmaxf(acc[mt][nt][3] * ia1 * ib1, -1.f), 1.f);
            int i = i0 + li;
            int j = j0 + lj;
            *(float2*)&dT[(size_t)i * 256 + j]       = v0;
            *(float2*)&dT[(size_t)(i + 8) * 256 + j] = v1;
        }
    }
}

// ---------------------------------------------------------------------------
// Kernel 2: banded DTW (R14 exact — best validated DTW, 62.3us): systolic
// staircase, 8-deep fully-unrolled register ring, act-predication removed
// (zero-filled invalid slots; BIG self-propagates; r>255 garbage unread).
// ---------------------------------------------------------------------------
__global__ __launch_bounds__(128) void dtw_kernel(float* __restrict__ out) {
    int w     = threadIdx.x >> 5;
    int lane  = threadIdx.x & 31;
    int batch = blockIdx.x * 4 + w;
    const float* E = g_dist + (size_t)batch * 65536;
    int jb = lane * 8;

    float d1[8];
#pragma unroll
    for (int u = 0; u < 8; u++) d1[u] = BIGF;
    float last7 = BIGF, prev7 = BIGF;
    float result = 0.f;

    float4 pf[8][2];
#pragma unroll
    for (int p = 0; p < 8; p++) {
        int r = p - lane;
        if (r >= 0) {
            const float* src = E + (size_t)r * 256 + jb;
            pf[p][0] = *(const float4*)src;
            pf[p][1] = *(const float4*)(src + 4);
        } else {
            pf[p][0] = make_float4(0.f, 0.f, 0.f, 0.f);
            pf[p][1] = make_float4(0.f, 0.f, 0.f, 0.f);
        }
    }

#pragma unroll 1
    for (int tb = 0; tb < 288; tb += 8) {
#pragma unroll
        for (int p = 0; p < 8; p++) {
            int t = tb + p;
            int r = t - lane;

            float e[8];
            e[0] = pf[p][0].x; e[1] = pf[p][0].y; e[2] = pf[p][0].z; e[3] = pf[p][0].w;
            e[4] = pf[p][1].x; e[5] = pf[p][1].y; e[6] = pf[p][1].z; e[7] = pf[p][1].w;

            {
                int rl = r + 8;
                if ((unsigned)rl < 256u) {
                    const float* src = E + (size_t)rl * 256 + jb;
                    pf[p][0] = *(const float4*)src;
                    pf[p][1] = *(const float4*)(src + 4);
                }
            }

            float lf0 = __shfl_up_sync(0xffffffffu, last7, 1);  // (r,   jb-1)
            float ul0 = __shfl_up_sync(0xffffffffu, prev7, 1);  // (r-1, jb-1)

            float m[8];
            m[0] = fminf(d1[0], ul0);
#pragma unroll
            for (int u = 1; u < 8; u++) m[u] = fminf(d1[u], d1[u - 1]);

            float nv[8];
            if (lane == 0) {
                nv[0] = (r == 0) ? e[0] : ((r <= RBAND) ? d1[0] + e[0] : BIGF);
            } else {
                bool ib = (jb >= r - RBAND) && (jb <= r + RBAND);
                nv[0] = ib ? fminf(m[0], lf0) + e[0] : BIGF;
            }
#pragma unroll
            for (int u = 1; u < 8; u++) {
                int j = jb + u;
                bool ib = (j >= r - RBAND) && (j <= r + RBAND);
                nv[u] = ib ? fminf(m[u], nv[u - 1]) + e[u] : BIGF;
            }

#pragma unroll
            for (int u = 0; u < 8; u++) d1[u] = nv[u];
            prev7 = last7;
            last7 = nv[7];
            if (r == 255) result = nv[7];
        }
    }

    if (lane == 31) out[batch] = result;
}

// ---------------------------------------------------------------------------
extern "C" void kernel_launch(void* const* d_in, const int* in_sizes, int n_in,
                              void* d_out, int out_size) {
    const float* s1 = (const float*)d_in[0];
    const float* s2 = (const float*)d_in[1];
    float* out = (float*)d_out;

    cudaFuncSetAttribute(gemm_kernel, cudaFuncAttributeMaxDynamicSharedMemorySize, GEMM_SMEM);
    dim3 g(2, 2, BB);
    gemm_kernel<<<g, 256, GEMM_SMEM>>>(s1, s2);

    dtw_kernel<<<64, 128>>>(out);
}

// round 16
// speedup vs baseline: 1.0754x; 1.0107x over previous
#include <cuda_runtime.h>
#include <cuda_bf16.h>
#include <cstdint>

#define BB 256
#define NN 256
#define MM 256
#define DD 1024
#define RBAND 128
#define BIGF 1e30f

// dist row-major [b][i][j]
__device__ float g_dist[(size_t)BB * 256 * 256];

static __device__ __forceinline__ uint32_t smem_u32(const void* p) {
    uint32_t a;
    asm("{ .reg .u64 t; cvta.to.shared.u64 t, %1; cvt.u32.u64 %0, t; }" : "=r"(a) : "l"(p));
    return a;
}
static __device__ __forceinline__ void cp16(uint32_t dst, const void* src) {
    asm volatile("cp.async.cg.shared.global [%0], [%1], 16;\n" ::"r"(dst), "l"(src) : "memory");
}
static __device__ __forceinline__ void ldsm_x4(uint32_t& r0, uint32_t& r1, uint32_t& r2,
                                               uint32_t& r3, uint32_t addr) {
    asm volatile("ldmatrix.sync.aligned.m8n8.x4.shared.b16 {%0,%1,%2,%3}, [%4];"
                 : "=r"(r0), "=r"(r1), "=r"(r2), "=r"(r3) : "r"(addr));
}
static __device__ __forceinline__ uint2 cvt_f4_bf16(float4 a) {
    __nv_bfloat162 p0 = __floats2bfloat162_rn(a.x, a.y);
    __nv_bfloat162 p1 = __floats2bfloat162_rn(a.z, a.w);
    uint2 w;
    w.x = *reinterpret_cast<unsigned int*>(&p0);
    w.y = *reinterpret_cast<unsigned int*>(&p1);
    return w;
}

// ---------------------------------------------------------------------------
// Fused kernel (R11/R15 exact — best validated GEMM, ~150us).
// ---------------------------------------------------------------------------
#define KT 32
#define LDP 40
#define STG (128 * 32)
#define BF  (128 * LDP)
#define SM_STAGEA 0
#define SM_STAGEB (2 * STG * 4)
#define SM_AS     (4 * STG * 4)
#define SM_BS     (SM_AS + 2 * BF * 2)
#define SM_INVA   (SM_BS + 2 * BF * 2)
#define SM_INVB   (SM_INVA + 128 * 4)
#define GEMM_SMEM (SM_INVB + 128 * 4)

__global__ __launch_bounds__(256, 2) void gemm_kernel(const float* __restrict__ s1,
                                                      const float* __restrict__ s2) {
    extern __shared__ __align__(16) char sm[];
    float* stageA = (float*)(sm + SM_STAGEA);
    float* stageB = (float*)(sm + SM_STAGEB);
    __nv_bfloat16* As = (__nv_bfloat16*)(sm + SM_AS);
    __nv_bfloat16* Bs = (__nv_bfloat16*)(sm + SM_BS);
    float* invA_s = (float*)(sm + SM_INVA);
    float* invB_s = (float*)(sm + SM_INVB);

    int b  = blockIdx.z;
    int i0 = blockIdx.x * 128;
    int j0 = blockIdx.y * 128;
    int t    = threadIdx.x;
    int lane = t & 31;
    int w    = t >> 5;
    int wm = w & 1;
    int wn = w >> 1;
    int gid = lane >> 2;
    int tig = lane & 3;

    const float* Ag = s1 + (size_t)b * NN * DD + (size_t)i0 * DD;
    const float* Bg = s2 + (size_t)b * MM * DD + (size_t)j0 * DD;

    int lr = t >> 3;
    int lc = (t & 7) * 4;

    float acc[4][4][4];
#pragma unroll
    for (int mt = 0; mt < 4; mt++)
#pragma unroll
        for (int nt = 0; nt < 4; nt++)
#pragma unroll
            for (int c = 0; c < 4; c++) acc[mt][nt][c] = 0.f;

    float ssA[4] = {0.f, 0.f, 0.f, 0.f};
    float ssB[4] = {0.f, 0.f, 0.f, 0.f};

#pragma unroll
    for (int s = 0; s < 2; s++) {
#pragma unroll
        for (int r4 = 0; r4 < 4; r4++) {
            int row = lr + r4 * 32;
            cp16(smem_u32(&stageA[s * STG + row * 32 + lc]),
                 Ag + (size_t)row * DD + s * KT + lc);
            cp16(smem_u32(&stageB[s * STG + row * 32 + lc]),
                 Bg + (size_t)row * DD + s * KT + lc);
        }
        asm volatile("cp.async.commit_group;\n" ::: "memory");
    }

    int a_row_in = (lane & 15);
    int a_koff   = (lane >> 4) * 8;
    int b_row_in = ((lane >> 4) << 3) + (lane & 7);
    int b_koff   = ((lane >> 3) & 1) * 8;

    for (int kt = 0; kt < DD / KT; kt++) {
        int st = kt & 1;
        if (kt >= 30) {
            asm volatile("cp.async.wait_group 0;\n" ::: "memory");
        } else {
            asm volatile("cp.async.wait_group 1;\n" ::: "memory");
        }

#pragma unroll
        for (int r4 = 0; r4 < 4; r4++) {
            int row = lr + r4 * 32;
            float4 a4 = *(const float4*)&stageA[st * STG + row * 32 + lc];
            float4 b4 = *(const float4*)&stageB[st * STG + row * 32 + lc];
            ssA[r4] += a4.x * a4.x + a4.y * a4.y + a4.z * a4.z + a4.w * a4.w;
            ssB[r4] += b4.x * b4.x + b4.y * b4.y + b4.z * b4.z + b4.w * b4.w;
            *(uint2*)&As[st * BF + row * LDP + lc] = cvt_f4_bf16(a4);
            *(uint2*)&Bs[st * BF + row * LDP + lc] = cvt_f4_bf16(b4);
        }

        if (kt + 2 < DD / KT) {
#pragma unroll
            for (int r4 = 0; r4 < 4; r4++) {
                int row = lr + r4 * 32;
                cp16(smem_u32(&stageA[st * STG + row * 32 + lc]),
                     Ag + (size_t)row * DD + (kt + 2) * KT + lc);
                cp16(smem_u32(&stageB[st * STG + row * 32 + lc]),
                     Bg + (size_t)row * DD + (kt + 2) * KT + lc);
            }
            asm volatile("cp.async.commit_group;\n" ::: "memory");
        }

        __syncthreads();

#pragma unroll
        for (int kk = 0; kk < KT; kk += 16) {
            uint32_t af[4][4];
            uint32_t bf2[2][4];
#pragma unroll
            for (int mt = 0; mt < 4; mt++) {
                int arow = wm * 64 + mt * 16 + a_row_in;
                uint32_t addr = smem_u32(&As[st * BF + arow * LDP + kk + a_koff]);
                ldsm_x4(af[mt][0], af[mt][1], af[mt][2], af[mt][3], addr);
            }
#pragma unroll
            for (int ntp = 0; ntp < 2; ntp++) {
                int brow = wn * 32 + ntp * 16 + b_row_in;
                uint32_t addr = smem_u32(&Bs[st * BF + brow * LDP + kk + b_koff]);
                ldsm_x4(bf2[ntp][0], bf2[ntp][1], bf2[ntp][2], bf2[ntp][3], addr);
            }
#pragma unroll
            for (int mt = 0; mt < 4; mt++)
#pragma unroll
                for (int nt = 0; nt < 4; nt++) {
                    uint32_t b0 = bf2[nt >> 1][(nt & 1) * 2];
                    uint32_t b1 = bf2[nt >> 1][(nt & 1) * 2 + 1];
                    asm volatile(
                        "mma.sync.aligned.m16n8k16.row.col.f32.bf16.bf16.f32 "
                        "{%0,%1,%2,%3}, {%4,%5,%6,%7}, {%8,%9}, {%0,%1,%2,%3};\n"
                        : "+f"(acc[mt][nt][0]), "+f"(acc[mt][nt][1]),
                          "+f"(acc[mt][nt][2]), "+f"(acc[mt][nt][3])
                        : "r"(af[mt][0]), "r"(af[mt][1]), "r"(af[mt][2]), "r"(af[mt][3]),
                          "r"(b0), "r"(b1));
                }
        }
    }

#pragma unroll
    for (int r4 = 0; r4 < 4; r4++) {
#pragma unroll
        for (int o = 1; o < 8; o <<= 1) {
            ssA[r4] += __shfl_xor_sync(0xffffffffu, ssA[r4], o);
            ssB[r4] += __shfl_xor_sync(0xffffffffu, ssB[r4], o);
        }
        if ((lane & 7) == 0) {
            int row = lr + r4 * 32;
            invA_s[row] = 1.0f / fmaxf(sqrtf(ssA[r4]), 1e-12f);
            invB_s[row] = 1.0f / fmaxf(sqrtf(ssB[r4]), 1e-12f);
        }
    }
    __syncthreads();

    float* dT = g_dist + (size_t)b * 65536;
#pragma unroll
    for (int mt = 0; mt < 4; mt++) {
#pragma unroll
        for (int nt = 0; nt < 4; nt++) {
            int li = wm * 64 + mt * 16 + gid;
            int lj = wn * 32 + nt * 8 + tig * 2;
            float ia0 = invA_s[li];
            float ia1 = invA_s[li + 8];
            float ib0 = invB_s[lj];
            float ib1 = invB_s[lj + 1];
            float2 v0, v1;
            v0.x = 1.0f - fminf(fmaxf(acc[mt][nt][0] * ia0 * ib0, -1.f), 1.f);
            v0.y = 1.0f - fminf(fmaxf(acc[mt][nt][1] * ia0 * ib1, -1.f), 1.f);
            v1.x = 1.0f - fminf(fmaxf(acc[mt][nt][2] * ia1 * ib0, -1.f), 1.f);
            v1.y = 1.0f - fminf(fmaxf(acc[mt][nt][3] * ia1 * ib1, -1.f), 1.f);
            int i = i0 + li;
            int j = j0 + lj;
            *(float2*)&dT[(size_t)i * 256 + j]       = v0;
            *(float2*)&dT[(size_t)(i + 8) * 256 + j] = v1;
        }
    }
}

// ---------------------------------------------------------------------------
// Kernel 2: banded DTW — systolic staircase with the in-lane serial min-add
// chain COLLAPSED via min-plus algebra:
//   nv[u] = min(b[u], nv[u-1]+e[u]), nv[-1]=lf0
//     ==>  nv[u] = PE[u] + min(G[u], lf0)
// where PE = prefix-sum(e), g[k] = b[k]-PE[k], G = prefix-min(g) (Kogge-Stone,
// 3 levels). Cross-lane loop-carried cycle: shfl + FMNMX + FADD + SEL (~38cy).
// Band contiguity guarantees no min-plus path crosses a masked cell, so the
// closed form equals the recurrence. Row-0 cumsum / lane-0 / masking edge
// cases fold in (lf0=BIG at lane 0; b[0] special at lane 0; final ib SEL).
// 8-deep unrolled register prefetch ring as in R14.
// ---------------------------------------------------------------------------
__global__ __launch_bounds__(128) void dtw_kernel(float* __restrict__ out) {
    int w     = threadIdx.x >> 5;
    int lane  = threadIdx.x & 31;
    int batch = blockIdx.x * 4 + w;
    const float* E = g_dist + (size_t)batch * 65536;
    int jb = lane * 8;

    float d1[8];
#pragma unroll
    for (int u = 0; u < 8; u++) d1[u] = BIGF;
    float last7 = BIGF, prev7 = BIGF;
    float result = 0.f;

    float4 pf[8][2];
#pragma unroll
    for (int p = 0; p < 8; p++) {
        int r = p - lane;
        if (r >= 0) {
            const float* src = E + (size_t)r * 256 + jb;
            pf[p][0] = *(const float4*)src;
            pf[p][1] = *(const float4*)(src + 4);
        } else {
            pf[p][0] = make_float4(0.f, 0.f, 0.f, 0.f);
            pf[p][1] = make_float4(0.f, 0.f, 0.f, 0.f);
        }
    }

#pragma unroll 1
    for (int tb = 0; tb < 288; tb += 8) {
#pragma unroll
        for (int p = 0; p < 8; p++) {
            int t = tb + p;
            int r = t - lane;

            float e[8];
            e[0] = pf[p][0].x; e[1] = pf[p][0].y; e[2] = pf[p][0].z; e[3] = pf[p][0].w;
            e[4] = pf[p][1].x; e[5] = pf[p][1].y; e[6] = pf[p][1].z; e[7] = pf[p][1].w;

            {
                int rl = r + 8;
                if ((unsigned)rl < 256u) {
                    const float* src = E + (size_t)rl * 256 + jb;
                    pf[p][0] = *(const float4*)src;
                    pf[p][1] = *(const float4*)(src + 4);
                }
            }

            // prefix sums of e (off the carried cycles)
            float PE[8];
            PE[0] = e[0];
#pragma unroll
            for (int u = 1; u < 8; u++) PE[u] = PE[u - 1] + e[u];

            float lf0 = __shfl_up_sync(0xffffffffu, last7, 1);  // (r,   jb-1)
            float ul0 = __shfl_up_sync(0xffffffffu, prev7, 1);  // (r-1, jb-1)
            if (lane == 0) lf0 = BIGF;

            // band masks (j in [r-RBAND, r+RBAND])
            bool ib[8];
#pragma unroll
            for (int u = 0; u < 8; u++) {
                int j = jb + u;
                ib[u] = (j >= r - RBAND) && (j <= r + RBAND);
            }

            // b[u] = masked(m[u] + e[u]);  lane0 column 0 special (up-only)
            float bb[8];
            if (lane == 0) {
                bb[0] = (r == 0) ? e[0] : ((r <= RBAND) ? d1[0] + e[0] : BIGF);
            } else {
                float m0 = fminf(d1[0], ul0);
                bb[0] = ib[0] ? m0 + e[0] : BIGF;
            }
#pragma unroll
            for (int u = 1; u < 8; u++) {
                float m = fminf(d1[u], d1[u - 1]);
                bb[u] = ib[u] ? m + e[u] : BIGF;
            }

            // g[k] = b[k] - PE[k]; G = prefix-min(g) (Kogge-Stone)
            float G[8];
#pragma unroll
            for (int u = 0; u < 8; u++) G[u] = bb[u] - PE[u];
#pragma unroll
            for (int u = 7; u >= 1; u--) G[u] = fminf(G[u], G[u - 1]);
            // note: serial form above is actually prefix-min but serial; use KS:
            // (the two loops below finish the logarithmic combine for u>=2)
#pragma unroll
            for (int u = 7; u >= 2; u--) G[u] = fminf(G[u], G[u - 2]);
#pragma unroll
            for (int u = 7; u >= 4; u--) G[u] = fminf(G[u], G[u - 4]);

            // nv[u] = ib ? PE[u] + min(G[u], lf0) : BIG
            float nv[8];
#pragma unroll
            for (int u = 0; u < 8; u++) {
                float v = fminf(G[u], lf0) + PE[u];
                nv[u] = ib[u] ? v : BIGF;
            }
            if (lane == 0) {
                // column 0 carries no left dependency; nv[0] = b[0] exactly
                nv[0] = bb[0];
            }

#pragma unroll
            for (int u = 0; u < 8; u++) d1[u] = nv[u];
            prev7 = last7;
            last7 = nv[7];
            if (r == 255) result = nv[7];
        }
    }

    if (lane == 31) out[batch] = result;
}

// ---------------------------------------------------------------------------
extern "C" void kernel_launch(void* const* d_in, const int* in_sizes, int n_in,
                              void* d_out, int out_size) {
    const float* s1 = (const float*)d_in[0];
    const float* s2 = (const float*)d_in[1];
    float* out = (float*)d_out;

    cudaFuncSetAttribute(gemm_kernel, cudaFuncAttributeMaxDynamicSharedMemorySize, GEMM_SMEM);
    dim3 g(2, 2, BB);
    gemm_kernel<<<g, 256, GEMM_SMEM>>>(s1, s2);

    dtw_kernel<<<64, 128>>>(out);
}